// round 2
// baseline (speedup 1.0000x reference)
#include <cuda_runtime.h>
#include <cuda_bf16.h>

// Problem shape (fixed by reference)
#define BATCH 4096
#define SLOTS 26
#define MAX_NNZ 10
#define EMB 64
#define NUM_SLOTS (BATCH * SLOTS)          // 106496 (b,s) pairs
#define LANES_PER_SLOT 16                  // each lane owns a float4 (16 * 16B = 256B row)

__global__ __launch_bounds__(256) void emb_combine_kernel(
    const int* __restrict__ keys,    // [B, S, N]
    const int* __restrict__ mask,    // [B, S, N]  (bool serialized as int32; nonzero = valid)
    const float* __restrict__ table, // [VOCAB, EMB]
    float* __restrict__ out)         // [B, S, EMB]
{
    int gtid = blockIdx.x * blockDim.x + threadIdx.x;
    int slot = gtid >> 4;            // 16 threads per (b,s)
    int lane = gtid & 15;            // which float4 of the row
    if (slot >= NUM_SLOTS) return;

    const int base = slot * MAX_NNZ;

    float4 acc = make_float4(0.f, 0.f, 0.f, 0.f);
    int cnt = 0;

#pragma unroll
    for (int j = 0; j < MAX_NNZ; j++) {
        // keys/mask are pure streaming traffic: evict-first so they don't
        // displace table rows in L2 (table only half-fits in 126MB L2).
        int m = __ldcs(&mask[base + j]);
        int k = __ldcs(&keys[base + j]);
        if (m) {
            const float4* row = reinterpret_cast<const float4*>(table + (size_t)k * EMB);
            float4 v = __ldg(&row[lane]);   // table: default policy, keep in L2
            acc.x += v.x; acc.y += v.y; acc.z += v.z; acc.w += v.w;
            cnt++;
        }
    }

    // mean combiner: divide by max(count, 1)
    float inv = 1.0f / (float)(cnt > 0 ? cnt : 1);
    acc.x *= inv; acc.y *= inv; acc.z *= inv; acc.w *= inv;

    // output is write-once streaming: evict-first
    float4 res = acc;
    __stcs(reinterpret_cast<float4*>(out + (size_t)slot * EMB) + lane, res);
}

extern "C" void kernel_launch(void* const* d_in, const int* in_sizes, int n_in,
                              void* d_out, int out_size) {
    const int*   keys  = (const int*)d_in[0];
    const int*   mask  = (const int*)d_in[1];
    const float* table = (const float*)d_in[2];
    float*       out   = (float*)d_out;

    const int total_threads = NUM_SLOTS * LANES_PER_SLOT;  // 1,703,936
    const int block = 256;
    const int grid = (total_threads + block - 1) / block;
    emb_combine_kernel<<<grid, block>>>(keys, mask, table, out);
}

// round 5
// speedup vs baseline: 1.0067x; 1.0067x over previous
#include <cuda_runtime.h>
#include <cuda_bf16.h>

// Problem shape (fixed by reference)
#define BATCH 4096
#define SLOTS 26
#define MAX_NNZ 10
#define EMB 64
#define NUM_SLOTS (BATCH * SLOTS)          // 106496 (b,s) pairs
#define LANES_PER_SLOT 16                  // each lane owns a float4 (16 * 16B = 256B row)

// Force 8 blocks/SM (2048 threads) -> ptxas must fit 32 regs -> 100% occupancy.
// More resident warps => more outstanding gathers => better DRAM latency hiding.
__global__ __launch_bounds__(256, 8) void emb_combine_kernel(
    const int* __restrict__ keys,    // [B, S, N]
    const int* __restrict__ mask,    // [B, S, N]  (bool as int32; nonzero = valid)
    const float* __restrict__ table, // [VOCAB, EMB]
    float* __restrict__ out)         // [B, S, EMB]
{
    int gtid = blockIdx.x * blockDim.x + threadIdx.x;
    int slot = gtid >> 4;            // 16 threads per (b,s)
    int lane = gtid & 15;            // which float4 of the row
    if (slot >= NUM_SLOTS) return;

    const int base = slot * MAX_NNZ;

    // Fold mask into key upfront: mk >= 0 means valid. Keeps live state compact
    // (10 ints) so we fit in 32 regs without spilling.
    int mk[MAX_NNZ];
    int cnt = 0;
#pragma unroll
    for (int j = 0; j < MAX_NNZ; j++) {
        int m = __ldg(&mask[base + j]);
        int k = __ldg(&keys[base + j]);
        mk[j] = m ? k : -1;
        cnt += (m ? 1 : 0);
    }

    float4 acc = make_float4(0.f, 0.f, 0.f, 0.f);
#pragma unroll
    for (int j = 0; j < MAX_NNZ; j++) {
        if (mk[j] >= 0) {
            const float4* row = reinterpret_cast<const float4*>(table + (size_t)mk[j] * EMB);
            float4 v = __ldg(&row[lane]);
            acc.x += v.x; acc.y += v.y; acc.z += v.z; acc.w += v.w;
        }
    }

    // mean combiner: divide by max(count, 1)
    float inv = 1.0f / (float)(cnt > 0 ? cnt : 1);
    acc.x *= inv; acc.y *= inv; acc.z *= inv; acc.w *= inv;

    reinterpret_cast<float4*>(out + (size_t)slot * EMB)[lane] = acc;
}

extern "C" void kernel_launch(void* const* d_in, const int* in_sizes, int n_in,
                              void* d_out, int out_size) {
    const int*   keys  = (const int*)d_in[0];
    const int*   mask  = (const int*)d_in[1];
    const float* table = (const float*)d_in[2];
    float*       out   = (float*)d_out;

    const int total_threads = NUM_SLOTS * LANES_PER_SLOT;  // 1,703,936
    const int block = 256;
    const int grid = (total_threads + block - 1) / block;
    emb_combine_kernel<<<grid, block>>>(keys, mask, table, out);
}

// round 6
// speedup vs baseline: 1.0727x; 1.0656x over previous
#include <cuda_runtime.h>
#include <cuda_bf16.h>

// Problem shape (fixed by reference)
#define BATCH 4096
#define SLOTS 26
#define MAX_NNZ 10
#define EMB 64
#define NUM_SLOTS (BATCH * SLOTS)          // 106496 (b,s) pairs
#define LANES_PER_SLOT 16                  // each lane owns a float4 (16 * 16B = 256B row)

// Total threads = NUM_SLOTS*16 = 1,703,936 = 6656 blocks * 256 exactly -> no tail,
// so full-warp shuffles/ballots are always safe.
__global__ __launch_bounds__(256, 6) void emb_combine_kernel(
    const int* __restrict__ keys,    // [B, S, N]
    const int* __restrict__ mask,    // [B, S, N]  (bool as int32; nonzero = valid)
    const float* __restrict__ table, // [VOCAB, EMB]
    float* __restrict__ out)         // [B, S, EMB]
{
    const int gtid   = blockIdx.x * blockDim.x + threadIdx.x;
    const int slot   = gtid >> 4;          // 16 threads per (b,s)
    const int lane16 = gtid & 15;          // which float4 of the 64-float row
    const unsigned lane = threadIdx.x & 31;
    const int halfbase  = lane & 16;       // 0 for low half-warp, 16 for high

    const int base = slot * MAX_NNZ;

    // Cooperative key/mask load: lane j (<10) of each half-warp loads entry j.
    // Was: every lane loads all 20 scalars (16x redundant, choked LSU issue).
    int mk = -1;
    if (lane16 < MAX_NNZ) {
        int m = __ldg(&mask[base + lane16]);
        int k = __ldg(&keys[base + lane16]);
        mk = m ? k : -1;
    }

    // Valid-count per half-warp via one ballot (lanes >= MAX_NNZ have mk = -1).
    unsigned ballot = __ballot_sync(0xFFFFFFFFu, mk >= 0);
    int cnt = __popc((ballot >> halfbase) & 0xFFFFu);

    float4 acc = make_float4(0.f, 0.f, 0.f, 0.f);

#pragma unroll
    for (int j = 0; j < MAX_NNZ; j++) {
        int kj = __shfl_sync(0xFFFFFFFFu, mk, halfbase + j);
        if (kj >= 0) {
            const float4* row = reinterpret_cast<const float4*>(table + (size_t)kj * EMB);
            float4 v = __ldg(&row[lane16]);
            acc.x += v.x; acc.y += v.y; acc.z += v.z; acc.w += v.w;
        }
    }

    // mean combiner: divide by max(count, 1)
    float inv = 1.0f / (float)(cnt > 0 ? cnt : 1);
    acc.x *= inv; acc.y *= inv; acc.z *= inv; acc.w *= inv;

    reinterpret_cast<float4*>(out + (size_t)slot * EMB)[lane16] = acc;
}

extern "C" void kernel_launch(void* const* d_in, const int* in_sizes, int n_in,
                              void* d_out, int out_size) {
    const int*   keys  = (const int*)d_in[0];
    const int*   mask  = (const int*)d_in[1];
    const float* table = (const float*)d_in[2];
    float*       out   = (float*)d_out;

    const int total_threads = NUM_SLOTS * LANES_PER_SLOT;  // 1,703,936
    const int block = 256;
    const int grid = (total_threads + block - 1) / block;  // 6656, exact
    emb_combine_kernel<<<grid, block>>>(keys, mask, table, out);
}

// round 10
// speedup vs baseline: 1.0884x; 1.0146x over previous
#include <cuda_runtime.h>
#include <cuda_bf16.h>

// Problem shape (fixed by reference)
#define BATCH 4096
#define SLOTS 26
#define MAX_NNZ 10
#define EMB 64
#define NUM_SLOTS (BATCH * SLOTS)          // 106496 (b,s) pairs
#define LANES_PER_SLOT 16                  // each lane owns a float4 (16 * 16B = 256B row)

// Total threads = NUM_SLOTS*16 = 1,703,936 = 6656 blocks * 256 exactly -> no tail,
// so full-warp shuffles/ballots are always safe.
//
// __launch_bounds__(256, 8): force <=32 regs -> 2048 threads/SM. Per-warp
// outstanding-LDG cap (~55) means deep per-thread front-batching is wasted;
// more resident warps converts directly into more outstanding gathers.
__global__ __launch_bounds__(256, 8) void emb_combine_kernel(
    const int* __restrict__ keys,    // [B, S, N]
    const int* __restrict__ mask,    // [B, S, N]  (bool as int32; nonzero = valid)
    const float* __restrict__ table, // [VOCAB, EMB]
    float* __restrict__ out)         // [B, S, EMB]
{
    const int gtid   = blockIdx.x * blockDim.x + threadIdx.x;
    const int slot   = gtid >> 4;          // 16 threads per (b,s)
    const int lane16 = gtid & 15;          // which float4 of the 64-float row
    const unsigned lane = threadIdx.x & 31;
    const int halfbase  = lane & 16;       // 0 for low half-warp, 16 for high

    const int base = slot * MAX_NNZ;

    // Cooperative key/mask load: lane j (<10) of each half-warp loads entry j.
    int mk = -1;
    if (lane16 < MAX_NNZ) {
        int m = __ldg(&mask[base + lane16]);
        int k = __ldg(&keys[base + lane16]);
        mk = m ? k : -1;
    }

    // Valid-count per half-warp via one ballot (lanes >= MAX_NNZ have mk = -1).
    unsigned ballot = __ballot_sync(0xFFFFFFFFu, mk >= 0);
    int cnt = __popc((ballot >> halfbase) & 0xFFFFu);

    float4 acc = make_float4(0.f, 0.f, 0.f, 0.f);

#pragma unroll
    for (int j = 0; j < MAX_NNZ; j++) {
        int kj = __shfl_sync(0xFFFFFFFFu, mk, halfbase + j);
        if (kj >= 0) {
            const float4* row = reinterpret_cast<const float4*>(table + (size_t)kj * EMB);
            float4 v = __ldg(&row[lane16]);
            acc.x += v.x; acc.y += v.y; acc.z += v.z; acc.w += v.w;
        }
    }

    // mean combiner: divide by max(count, 1)
    float inv = 1.0f / (float)(cnt > 0 ? cnt : 1);
    acc.x *= inv; acc.y *= inv; acc.z *= inv; acc.w *= inv;

    reinterpret_cast<float4*>(out + (size_t)slot * EMB)[lane16] = acc;
}

extern "C" void kernel_launch(void* const* d_in, const int* in_sizes, int n_in,
                              void* d_out, int out_size) {
    const int*   keys  = (const int*)d_in[0];
    const int*   mask  = (const int*)d_in[1];
    const float* table = (const float*)d_in[2];
    float*       out   = (float*)d_out;

    const int total_threads = NUM_SLOTS * LANES_PER_SLOT;  // 1,703,936
    const int block = 256;
    const int grid = (total_threads + block - 1) / block;  // 6656, exact
    emb_combine_kernel<<<grid, block>>>(keys, mask, table, out);
}